// round 8
// baseline (speedup 1.0000x reference)
#include <cuda_runtime.h>
#include <cstdint>

#define N_NODES 100000
#define FEAT 64
#define OUT_DIM 2

// Per-node projected message m = h @ W1  (L2-resident: 800 KB)
__device__ float2 g_m[N_NODES];

// ---------------------------------------------------------------------------
// Fused node kernel (296 blocks x 1024 thr):
//  1) warp-cooperative weight fold (32 warps x 4 pairs, coalesced, butterfly)
//  2) warp-per-node projection UNROLLED x4: 8 independent coalesced loads in
//     flight per warp iteration (fixes the MLP=2 latency bind seen at ~12us).
//   m[i] = h[i]@W1 (g_m);  out[i] = h[i]@W2 + bias
// ---------------------------------------------------------------------------
__global__ __launch_bounds__(1024, 2)
void node_kernel(const float* __restrict__ pos,
                 const float* __restrict__ vel,
                 const float* __restrict__ W_rel,
                 const float* __restrict__ b_rel,
                 const float* __restrict__ W_root,
                 const float* __restrict__ W_pred,
                 const float* __restrict__ b_pred,
                 float* __restrict__ out) {
    __shared__ float4 sW[FEAT];       // (W1[f][0], W1[f][1], W2[f][0], W2[f][1])
    __shared__ float  sbias[OUT_DIM];

    int t    = threadIdx.x;
    int warp = t >> 5;                // 0..31
    int lane = t & 31;

    // ---- fold: 32 warps x 4 (k,o)-pairs = 128 entries ----
    #pragma unroll
    for (int i = 0; i < 4; ++i) {
        int p = warp * 4 + i;
        int k = p >> 1;
        int o = p & 1;
        float wp0 = W_pred[lane * OUT_DIM + o];
        float wp1 = W_pred[(lane + 32) * OUT_DIM + o];
        float s1 = W_rel [k * FEAT + lane] * wp0 + W_rel [k * FEAT + lane + 32] * wp1;
        float s2 = W_root[k * FEAT + lane] * wp0 + W_root[k * FEAT + lane + 32] * wp1;
        #pragma unroll
        for (int off = 16; off > 0; off >>= 1) {
            s1 += __shfl_xor_sync(0xffffffffu, s1, off);
            s2 += __shfl_xor_sync(0xffffffffu, s2, off);
        }
        if (lane == 0) {
            float* w = (float*)&sW[k];
            w[o]     = s1;
            w[2 + o] = s2;
        }
    }
    if (warp < OUT_DIM) {
        int o = warp;
        float bb = b_rel[lane]      * W_pred[lane * OUT_DIM + o]
                 + b_rel[lane + 32] * W_pred[(lane + 32) * OUT_DIM + o];
        #pragma unroll
        for (int off = 16; off > 0; off >>= 1)
            bb += __shfl_xor_sync(0xffffffffu, bb, off);
        if (lane == 0) sbias[o] = bb + b_pred[o];
    }
    __syncthreads();

    // per-lane folded weights in registers
    float4 wpk = sW[lane];            // weights for pos feature `lane`
    float4 wvk = sW[32 + lane];       // weights for vel feature `lane+32`
    float bias0 = sbias[0], bias1 = sbias[1];

    // ---- node phase: warp handles 4 nodes per iteration ----
    int wg    = blockIdx.x * 32 + warp;
    int total = gridDim.x * 32;       // 9472 warps

    for (int n0 = wg * 4; n0 < N_NODES; n0 += total * 4) {
        // N_NODES % 4 == 0 -> n0..n0+3 all valid
        float p0 = __ldcs(pos + (n0 + 0) * 32 + lane);
        float p1 = __ldcs(pos + (n0 + 1) * 32 + lane);
        float p2 = __ldcs(pos + (n0 + 2) * 32 + lane);
        float p3 = __ldcs(pos + (n0 + 3) * 32 + lane);
        float v0 = __ldcs(vel + (n0 + 0) * 32 + lane);
        float v1 = __ldcs(vel + (n0 + 1) * 32 + lane);
        float v2 = __ldcs(vel + (n0 + 2) * 32 + lane);
        float v3 = __ldcs(vel + (n0 + 3) * 32 + lane);

        float m0[4], m1[4], r0[4], r1[4];
        float P[4] = {p0, p1, p2, p3};
        float V[4] = {v0, v1, v2, v3};
        #pragma unroll
        for (int j = 0; j < 4; ++j) {
            m0[j] = P[j] * wpk.x + V[j] * wvk.x;
            m1[j] = P[j] * wpk.y + V[j] * wvk.y;
            r0[j] = P[j] * wpk.z + V[j] * wvk.z;
            r1[j] = P[j] * wpk.w + V[j] * wvk.w;
        }
        #pragma unroll
        for (int off = 16; off > 0; off >>= 1) {
            #pragma unroll
            for (int j = 0; j < 4; ++j) {
                m0[j] += __shfl_xor_sync(0xffffffffu, m0[j], off);
                m1[j] += __shfl_xor_sync(0xffffffffu, m1[j], off);
                r0[j] += __shfl_xor_sync(0xffffffffu, r0[j], off);
                r1[j] += __shfl_xor_sync(0xffffffffu, r1[j], off);
            }
        }
        if (lane == 0) {
            #pragma unroll
            for (int j = 0; j < 4; ++j) {
                g_m[n0 + j] = make_float2(m0[j], m1[j]);
                ((float2*)out)[n0 + j] = make_float2(r0[j] + bias0, r1[j] + bias1);
            }
        }
    }
}

// ---------------------------------------------------------------------------
// Edge kernel: 8 edges/thread as two 4-edge halves (keeps regs <= 32 so
// __launch_bounds__(256, 8) yields 2048 threads/SM — vs 1536 at 40 regs,
// where L2 sat at 66%). out[dst] += m[src] via vector RED (L2 atomics).
// 1184 blocks = 148 SMs x 8 blocks: exactly one resident wave, grid-stride.
// ---------------------------------------------------------------------------
__device__ __forceinline__ void red_v2(float* addr, float2 v) {
    asm volatile("red.global.add.v2.f32 [%0], {%1, %2};"
                 :: "l"(addr), "f"(v.x), "f"(v.y) : "memory");
}

__global__ __launch_bounds__(256, 8)
void edge_kernel(const int* __restrict__ src,
                 const int* __restrict__ dst,
                 float* __restrict__ out,
                 int n_edges) {
    int tid = blockIdx.x * blockDim.x + threadIdx.x;
    int NT  = gridDim.x * blockDim.x;
    int n8  = n_edges & ~7;

    for (int base = tid * 8; base < n8; base += NT * 8) {
        int4 s0 = __ldcs((const int4*)(src + base));
        int4 s1 = __ldcs((const int4*)(src + base + 4));
        int4 d0 = __ldcs((const int4*)(dst + base));
        int4 d1 = __ldcs((const int4*)(dst + base + 4));
        // first half
        float2 a0 = g_m[s0.x];
        float2 a1 = g_m[s0.y];
        float2 a2 = g_m[s0.z];
        float2 a3 = g_m[s0.w];
        red_v2(out + 2 * d0.x, a0);
        red_v2(out + 2 * d0.y, a1);
        red_v2(out + 2 * d0.z, a2);
        red_v2(out + 2 * d0.w, a3);
        // second half (s0/d0 registers dead here -> lower peak pressure)
        float2 b0 = g_m[s1.x];
        float2 b1 = g_m[s1.y];
        float2 b2 = g_m[s1.z];
        float2 b3 = g_m[s1.w];
        red_v2(out + 2 * d1.x, b0);
        red_v2(out + 2 * d1.y, b1);
        red_v2(out + 2 * d1.z, b2);
        red_v2(out + 2 * d1.w, b3);
    }
    if (tid == 0) {                   // tail (n_edges % 8; empty for 3.2M)
        for (int i = n8; i < n_edges; ++i) {
            float2 mm = g_m[src[i]];
            red_v2(out + 2 * dst[i], mm);
        }
    }
}

// ---------------------------------------------------------------------------
// Launch
// Inputs (metadata order): pos, vel, edge_index, W_rel, b_rel, W_root, W_pred, b_pred
// ---------------------------------------------------------------------------
extern "C" void kernel_launch(void* const* d_in, const int* in_sizes, int n_in,
                              void* d_out, int out_size) {
    const float* pos    = (const float*)d_in[0];
    const float* vel    = (const float*)d_in[1];
    const int*   eidx   = (const int*)  d_in[2];
    const float* W_rel  = (const float*)d_in[3];
    const float* b_rel  = (const float*)d_in[4];
    const float* W_root = (const float*)d_in[5];
    const float* W_pred = (const float*)d_in[6];
    const float* b_pred = (const float*)d_in[7];
    float* out = (float*)d_out;

    const int n_edges = in_sizes[2] / 2;          // 3.2M
    const int* src = eidx;
    const int* dst = eidx + n_edges;

    node_kernel<<<296, 1024>>>(pos, vel, W_rel, b_rel, W_root,
                               W_pred, b_pred, out);

    edge_kernel<<<1184, 256>>>(src, dst, out, n_edges);
}

// round 9
// speedup vs baseline: 1.2356x; 1.2356x over previous
#include <cuda_runtime.h>
#include <cstdint>

#define N_NODES 100000
#define FEAT 64
#define OUT_DIM 2

// Per-node projected message m = h @ W1  (L2-resident: 800 KB)
__device__ float2 g_m[N_NODES];

// ---------------------------------------------------------------------------
// Fused node kernel (296 blocks x 1024 thr):
//  1) warp-cooperative weight fold (32 warps x 4 pairs)
//  2) warp-per-node x4 unroll with MULTI-VALUE butterfly: all 4 accumulators
//     (m0,m1,r0,r1) reduced in 6 shuffles (vs 20) by routing each value to its
//     own 8-lane quarter. Lanes 0/8/16/24 end with the 4 totals.
// ---------------------------------------------------------------------------
__global__ __launch_bounds__(1024, 2)
void node_kernel(const float* __restrict__ pos,
                 const float* __restrict__ vel,
                 const float* __restrict__ W_rel,
                 const float* __restrict__ b_rel,
                 const float* __restrict__ W_root,
                 const float* __restrict__ W_pred,
                 const float* __restrict__ b_pred,
                 float* __restrict__ out) {
    __shared__ float4 sW[FEAT];       // (W1[f][0], W1[f][1], W2[f][0], W2[f][1])
    __shared__ float  sbias[OUT_DIM];

    int t    = threadIdx.x;
    int warp = t >> 5;                // 0..31
    int lane = t & 31;

    // ---- fold: 32 warps x 4 (k,o)-pairs ----
    #pragma unroll
    for (int i = 0; i < 4; ++i) {
        int p = warp * 4 + i;
        int k = p >> 1;
        int o = p & 1;
        float wp0 = W_pred[lane * OUT_DIM + o];
        float wp1 = W_pred[(lane + 32) * OUT_DIM + o];
        float s1 = W_rel [k * FEAT + lane] * wp0 + W_rel [k * FEAT + lane + 32] * wp1;
        float s2 = W_root[k * FEAT + lane] * wp0 + W_root[k * FEAT + lane + 32] * wp1;
        #pragma unroll
        for (int off = 16; off > 0; off >>= 1) {
            s1 += __shfl_xor_sync(0xffffffffu, s1, off);
            s2 += __shfl_xor_sync(0xffffffffu, s2, off);
        }
        if (lane == 0) {
            float* w = (float*)&sW[k];
            w[o]     = s1;
            w[2 + o] = s2;
        }
    }
    if (warp < OUT_DIM) {
        int o = warp;
        float bb = b_rel[lane]      * W_pred[lane * OUT_DIM + o]
                 + b_rel[lane + 32] * W_pred[(lane + 32) * OUT_DIM + o];
        #pragma unroll
        for (int off = 16; off > 0; off >>= 1)
            bb += __shfl_xor_sync(0xffffffffu, bb, off);
        if (lane == 0) sbias[o] = bb + b_pred[o];
    }
    __syncthreads();

    float4 wpk = sW[lane];            // weights for pos feature `lane`
    float4 wvk = sW[32 + lane];       // weights for vel feature `lane+32`
    float bias0 = sbias[0], bias1 = sbias[1];

    bool laneSel = (lane & 7) == 0;   // lanes 0,8,16,24 write results
    bool isM     = (lane & 8) == 0;   // 0,16 -> g_m ; 8,24 -> out
    int  hi      = lane >> 4;         // component 0 or 1

    int wg    = blockIdx.x * 32 + warp;
    int total = gridDim.x * 32;       // 9472 warps

    for (int n0 = wg * 4; n0 < N_NODES; n0 += total * 4) {
        // N_NODES % 4 == 0 -> all 4 valid. 8 independent coalesced loads.
        float P[4], V[4];
        #pragma unroll
        for (int j = 0; j < 4; ++j) P[j] = __ldcs(pos + (n0 + j) * 32 + lane);
        #pragma unroll
        for (int j = 0; j < 4; ++j) V[j] = __ldcs(vel + (n0 + j) * 32 + lane);

        float y[4];
        #pragma unroll
        for (int j = 0; j < 4; ++j) {
            float m0 = P[j] * wpk.x + V[j] * wvk.x;
            float m1 = P[j] * wpk.y + V[j] * wvk.y;
            float r0 = P[j] * wpk.z + V[j] * wvk.z;
            float r1 = P[j] * wpk.w + V[j] * wvk.w;

            // round 1 (off=16): halves -> low:m0, high:m1 | low:r0, high:r1
            float xA = (lane & 16) ? m1 : m0;
            float gA = (lane & 16) ? m0 : m1;
            xA += __shfl_xor_sync(0xffffffffu, gA, 16);
            float xB = (lane & 16) ? r1 : r0;
            float gB = (lane & 16) ? r0 : r1;
            xB += __shfl_xor_sync(0xffffffffu, gB, 16);
            // round 2 (off=8): quarters -> [m0|r0|m1|r1]
            float yy = (lane & 8) ? xB : xA;
            float gg = (lane & 8) ? xA : xB;
            yy += __shfl_xor_sync(0xffffffffu, gg, 8);
            // rounds 3-5: butterfly within each 8-lane group
            yy += __shfl_xor_sync(0xffffffffu, yy, 4);
            yy += __shfl_xor_sync(0xffffffffu, yy, 2);
            yy += __shfl_xor_sync(0xffffffffu, yy, 1);
            y[j] = yy;
        }

        // lanes 0,16 store g_m[n].{x,y}; lanes 8,24 store out[2n+{0,1}]
        if (laneSel) {
            #pragma unroll
            for (int j = 0; j < 4; ++j) {
                int n = n0 + j;
                if (isM) ((float*)&g_m[n])[hi] = y[j];
                else     out[2 * n + hi] = y[j] + (hi ? bias1 : bias0);
            }
        }
    }
}

// ---------------------------------------------------------------------------
// Edge kernel: EXACT R3 config (proven 31.9us): 8 edges/thread, single pass,
// natural regs (~40), 1563 blocks x 256. All 8 gathers issued before REDs.
// ---------------------------------------------------------------------------
__device__ __forceinline__ void red_v2(float* addr, float2 v) {
    asm volatile("red.global.add.v2.f32 [%0], {%1, %2};"
                 :: "l"(addr), "f"(v.x), "f"(v.y) : "memory");
}

__global__ void edge_kernel(const int* __restrict__ src,
                            const int* __restrict__ dst,
                            float* __restrict__ out,
                            int n_edges) {
    int t = blockIdx.x * blockDim.x + threadIdx.x;
    int base = t * 8;
    if (base + 7 < n_edges) {
        int4 s0 = __ldcs((const int4*)(src + base));
        int4 s1 = __ldcs((const int4*)(src + base + 4));
        int4 d0 = __ldcs((const int4*)(dst + base));
        int4 d1 = __ldcs((const int4*)(dst + base + 4));
        float2 a0 = g_m[s0.x];
        float2 a1 = g_m[s0.y];
        float2 a2 = g_m[s0.z];
        float2 a3 = g_m[s0.w];
        float2 b0 = g_m[s1.x];
        float2 b1 = g_m[s1.y];
        float2 b2 = g_m[s1.z];
        float2 b3 = g_m[s1.w];
        red_v2(out + 2 * d0.x, a0);
        red_v2(out + 2 * d0.y, a1);
        red_v2(out + 2 * d0.z, a2);
        red_v2(out + 2 * d0.w, a3);
        red_v2(out + 2 * d1.x, b0);
        red_v2(out + 2 * d1.y, b1);
        red_v2(out + 2 * d1.z, b2);
        red_v2(out + 2 * d1.w, b3);
    } else {
        for (int i = base; i < n_edges; ++i) {
            float2 mm = g_m[src[i]];
            red_v2(out + 2 * dst[i], mm);
        }
    }
}

// ---------------------------------------------------------------------------
// Launch
// Inputs (metadata order): pos, vel, edge_index, W_rel, b_rel, W_root, W_pred, b_pred
// ---------------------------------------------------------------------------
extern "C" void kernel_launch(void* const* d_in, const int* in_sizes, int n_in,
                              void* d_out, int out_size) {
    const float* pos    = (const float*)d_in[0];
    const float* vel    = (const float*)d_in[1];
    const int*   eidx   = (const int*)  d_in[2];
    const float* W_rel  = (const float*)d_in[3];
    const float* b_rel  = (const float*)d_in[4];
    const float* W_root = (const float*)d_in[5];
    const float* W_pred = (const float*)d_in[6];
    const float* b_pred = (const float*)d_in[7];
    float* out = (float*)d_out;

    const int n_edges = in_sizes[2] / 2;          // 3.2M
    const int* src = eidx;
    const int* dst = eidx + n_edges;

    node_kernel<<<296, 1024>>>(pos, vel, W_rel, b_rel, W_root,
                               W_pred, b_pred, out);

    int n_thr = (n_edges + 7) / 8;
    edge_kernel<<<(n_thr + 255) / 256, 256>>>(src, dst, out, n_edges);
}